// round 2
// baseline (speedup 1.0000x reference)
#include <cuda_runtime.h>
#include <math.h>

#define BN   512     // B*N
#define FEAT 384
#define FFN  768
#define ZD   384
#define HID  192
#define NB   4
#define NN   128
#define LN_EPS 1e-5f

// ---------------- scratch (device globals; no allocation) ----------------
__device__ float g_xh[BN * ZD];     // gelu'd first half
__device__ float g_z[BN * ZD];      // second half: raw gelu, then LN'd in-place
__device__ float g_c0[ZD];          // gelu(enc_b) @ dec_w + dec_b
__device__ float g_diag[BN];
__device__ float g_off[BN];
__device__ float g_T[NB * ZD];      // sum_j e_off[j] * xh[b,j,:]
__device__ float g_wd[BN];          // e_diag - e_off
__device__ float g_rD[BN];          // 1 / (S - e_off + e_diag)

__device__ __forceinline__ float gelu_exact(float x) {
    return 0.5f * x * (1.0f + erff(x * 0.70710678118654752440f));
}

// ---------------- k0: c0 = gelu(enc_b) @ dec_w + dec_b -------------------
__global__ void k0_c0(const float* __restrict__ enc_b,
                      const float* __restrict__ dec_w,
                      const float* __restrict__ dec_b) {
    __shared__ float gh[HID];
    int t = threadIdx.x;                 // 0..383
    if (t < HID) gh[t] = gelu_exact(enc_b[t]);
    __syncthreads();
    float acc = dec_b[t];
#pragma unroll 4
    for (int u = 0; u < HID; u++) acc += gh[u] * dec_w[u * ZD + t];
    g_c0[t] = acc;
}

// ---------------- k1: h = gelu(x @ U_w + U_b); split into xh / z ----------
// grid (2 col-halves, 64 row-groups), block 384. 8 rows per block.
__global__ void k1_gemmU(const float* __restrict__ x,
                         const float* __restrict__ U_w,
                         const float* __restrict__ U_b) {
    const int half = blockIdx.x;          // 0 -> xh cols, 1 -> z cols
    const int r0   = blockIdx.y * 8;
    const int j    = threadIdx.x;         // 0..383
    __shared__ float xs[8][FEAT];
    for (int i = j; i < 8 * FEAT; i += 384) {
        int r = i / FEAT, k = i % FEAT;
        xs[r][k] = x[(r0 + r) * FEAT + k];
    }
    __syncthreads();
    float acc[8];
    const float b = U_b[half * ZD + j];
#pragma unroll
    for (int r = 0; r < 8; r++) acc[r] = b;
    const float* wcol = U_w + half * ZD + j;
#pragma unroll 4
    for (int k = 0; k < FEAT; k++) {
        float w = wcol[(size_t)k * FFN];
#pragma unroll
        for (int r = 0; r < 8; r++) acc[r] += xs[r][k] * w;
    }
    if (half == 0) {
#pragma unroll
        for (int r = 0; r < 8; r++) g_xh[(r0 + r) * ZD + j] = gelu_exact(acc[r]);
    } else {
#pragma unroll
        for (int r = 0; r < 8; r++) g_z[(r0 + r) * ZD + j] = gelu_exact(acc[r]);
    }
}

// ---------------- k1b: LayerNorm z in place -------------------------------
__global__ void k1b_ln(const float* __restrict__ ln_w,
                       const float* __restrict__ ln_b) {
    const int row = blockIdx.x;
    const int j   = threadIdx.x;          // 0..383  (12 warps)
    float v = g_z[row * ZD + j];
    __shared__ float s1[12], s2[12];
    float a = v, bb = v * v;
#pragma unroll
    for (int o = 16; o > 0; o >>= 1) {
        a  += __shfl_down_sync(0xffffffffu, a, o);
        bb += __shfl_down_sync(0xffffffffu, bb, o);
    }
    int w = j >> 5, l = j & 31;
    if (l == 0) { s1[w] = a; s2[w] = bb; }
    __syncthreads();
    if (w == 0) {
        a  = (l < 12) ? s1[l] : 0.f;
        bb = (l < 12) ? s2[l] : 0.f;
#pragma unroll
        for (int o = 16; o > 0; o >>= 1) {
            a  += __shfl_down_sync(0xffffffffu, a, o);
            bb += __shfl_down_sync(0xffffffffu, bb, o);
        }
        if (l == 0) { s1[0] = a; s2[0] = bb; }
    }
    __syncthreads();
    float mu  = s1[0] * (1.0f / ZD);
    float var = s2[0] * (1.0f / ZD) - mu * mu;
    float rs  = rsqrtf(var + LN_EPS);
    g_z[row * ZD + j] = (v - mu) * rs * ln_w[j] + ln_b[j];
}

// ---------------- k2: AE on diagonal + both dot products ------------------
// block 192 threads per row
__global__ void k2_ae(const float* __restrict__ enc_w,
                      const float* __restrict__ enc_b,
                      const float* __restrict__ dec_w,
                      const float* __restrict__ dec_b) {
    const int row = blockIdx.x;
    const int t   = threadIdx.x;          // 0..191 (6 warps)
    __shared__ float zs[ZD];
    __shared__ float hs[HID];
    zs[t]       = g_z[row * ZD + t];
    zs[t + HID] = g_z[row * ZD + t + HID];
    __syncthreads();
    float acc = enc_b[t];
#pragma unroll 4
    for (int k = 0; k < ZD; k++) acc += zs[k] * enc_w[k * HID + t];
    hs[t] = gelu_exact(acc);
    __syncthreads();
    const int f0 = t, f1 = t + HID;
    float p0 = dec_b[f0], p1 = dec_b[f1];
#pragma unroll 4
    for (int u = 0; u < HID; u++) {
        float h = hs[u];
        p0 += h * dec_w[u * ZD + f0];
        p1 += h * dec_w[u * ZD + f1];
    }
    float dpart = p0 * zs[f0] + p1 * zs[f1];
    float opart = g_c0[f0] * zs[f0] + g_c0[f1] * zs[f1];
    __shared__ float r1[6], r2[6];
#pragma unroll
    for (int o = 16; o > 0; o >>= 1) {
        dpart += __shfl_down_sync(0xffffffffu, dpart, o);
        opart += __shfl_down_sync(0xffffffffu, opart, o);
    }
    int w = t >> 5, l = t & 31;
    if (l == 0) { r1[w] = dpart; r2[w] = opart; }
    __syncthreads();
    if (t == 0) {
        float d = 0.f, o = 0.f;
#pragma unroll
        for (int i = 0; i < 6; i++) { d += r1[i]; o += r2[i]; }
        g_diag[row] = d;
        g_off[row]  = o;
    }
}

// ---------------- k3: per-batch softmax stats + T aggregation -------------
// grid 4 blocks (one per batch), block 384
__global__ void k3_softmax() {
    const int b = blockIdx.x;
    const int t = threadIdx.x;            // 0..383
    __shared__ float eo[NN], ed[NN];
    __shared__ float red[13];
    float off = -1e30f, dg = -1e30f;
    if (t < NN) { off = g_off[b * NN + t]; dg = g_diag[b * NN + t]; }
    float m = fmaxf(off, dg);
#pragma unroll
    for (int o = 16; o > 0; o >>= 1) m = fmaxf(m, __shfl_down_sync(0xffffffffu, m, o));
    int w = t >> 5, l = t & 31;
    if (l == 0) red[w] = m;
    __syncthreads();
    if (t == 0) {
        float mm = -1e30f;
#pragma unroll
        for (int i = 0; i < 12; i++) mm = fmaxf(mm, red[i]);
        red[12] = mm;
    }
    __syncthreads();
    m = red[12];
    float e1 = 0.f;
    if (t < NN) {
        float a = expf(off - m), c = expf(dg - m);
        eo[t] = a; ed[t] = c;
        e1 = a;
    }
    __syncthreads();   // everyone has read red[12]
#pragma unroll
    for (int o = 16; o > 0; o >>= 1) e1 += __shfl_down_sync(0xffffffffu, e1, o);
    if (l == 0) red[w] = e1;
    __syncthreads();
    if (t == 0) {
        float s = 0.f;
#pragma unroll
        for (int i = 0; i < 12; i++) s += red[i];
        red[12] = s;
    }
    __syncthreads();
    const float S = red[12];
    if (t < NN) {
        float a = eo[t], c = ed[t];
        g_wd[b * NN + t] = c - a;
        g_rD[b * NN + t] = 1.0f / (S - a + c);
    }
    // T[f] = sum_j e_off[j] * xh[b,j,f]
    float acc = 0.f;
    const float* xh = g_xh + (size_t)b * NN * ZD + t;
#pragma unroll 4
    for (int j = 0; j < NN; j++) acc += eo[j] * xh[(size_t)j * ZD];
    g_T[b * ZD + t] = acc;
}

// ---------------- k4: combine + final GEMM (out = u @ V_w + V_b) ----------
// grid 128 blocks (4 rows each), block 384
__global__ void k4_out(const float* __restrict__ V_w,
                       const float* __restrict__ V_b,
                       float* __restrict__ out) {
    const int r0 = blockIdx.x * 4;
    const int g  = threadIdx.x;           // 0..383
    const int b  = r0 / NN;               // 4 rows never straddle a batch (128 % 4 == 0)
    __shared__ float us[4][ZD];
#pragma unroll
    for (int r = 0; r < 4; r++) {
        int row = r0 + r;
        us[r][g] = (g_T[b * ZD + g] + g_wd[row] * g_xh[row * ZD + g]) * g_rD[row];
    }
    __syncthreads();
    float acc[4];
    const float vb = V_b[g];
#pragma unroll
    for (int r = 0; r < 4; r++) acc[r] = vb;
    const float* wc = V_w + g;
#pragma unroll 4
    for (int f = 0; f < ZD; f++) {
        float w = wc[(size_t)f * FEAT];
#pragma unroll
        for (int r = 0; r < 4; r++) acc[r] += us[r][f] * w;
    }
#pragma unroll
    for (int r = 0; r < 4; r++) out[(r0 + r) * FEAT + g] = acc[r];
}

// ---------------- launch ---------------------------------------------------
extern "C" void kernel_launch(void* const* d_in, const int* in_sizes, int n_in,
                              void* d_out, int out_size) {
    const float* x     = (const float*)d_in[0];
    const float* U_w   = (const float*)d_in[1];
    const float* U_b   = (const float*)d_in[2];
    const float* ln_w  = (const float*)d_in[3];
    const float* ln_b  = (const float*)d_in[4];
    const float* enc_w = (const float*)d_in[5];
    const float* enc_b = (const float*)d_in[6];
    const float* dec_w = (const float*)d_in[7];
    const float* dec_b = (const float*)d_in[8];
    const float* V_w   = (const float*)d_in[9];
    const float* V_b   = (const float*)d_in[10];
    float* out = (float*)d_out;

    k0_c0<<<1, 384>>>(enc_b, dec_w, dec_b);
    dim3 g1(2, 64);
    k1_gemmU<<<g1, 384>>>(x, U_w, U_b);
    k1b_ln<<<BN, 384>>>(ln_w, ln_b);
    k2_ae<<<BN, 192>>>(enc_w, enc_b, dec_w, dec_b);
    k3_softmax<<<NB, 384>>>();
    k4_out<<<NN, 384>>>(V_w, V_b, out);
}

// round 3
// speedup vs baseline: 1.1109x; 1.1109x over previous
#include <cuda_runtime.h>
#include <math.h>

#define BN   512     // B*N
#define FEAT 384
#define FFN  768
#define ZD   384
#define HID  192
#define NB   4
#define NN   128
#define LN_EPS 1e-5f

// ---------------- scratch (device globals; no allocation) ----------------
__device__ float g_xh[BN * ZD];     // gelu'd first half
__device__ float g_z[BN * ZD];      // LN'd second half
__device__ float g_c0[ZD];          // gelu(enc_b) @ dec_w + dec_b
__device__ float g_diag[BN];
__device__ float g_off[BN];
__device__ float g_T[NB * ZD];      // sum_j e_off[j] * xh[b,j,:]
__device__ float g_wd[BN];          // e_diag - e_off
__device__ float g_rD[BN];          // 1 / (S - e_off + e_diag)

__device__ __forceinline__ float gelu_exact(float x) {
    return 0.5f * x * (1.0f + erff(x * 0.70710678118654752440f));
}

// ---------------- k0: c0 = gelu(enc_b) @ dec_w + dec_b -------------------
__global__ void k0_c0(const float* __restrict__ enc_b,
                      const float* __restrict__ dec_w,
                      const float* __restrict__ dec_b) {
    __shared__ float gh[HID];
    int t = threadIdx.x;                 // 0..383
    if (t < HID) gh[t] = gelu_exact(enc_b[t]);
    __syncthreads();
    float acc = dec_b[t];
#pragma unroll 4
    for (int u = 0; u < HID; u++) acc += gh[u] * dec_w[u * ZD + t];
    g_c0[t] = acc;
}

// ---------------- k1: h = gelu(x @ U_w + U_b); xh half / z half (+LN) -----
// grid (2 col-halves, 64 row-groups), block 384. 8 rows per block.
__global__ void k1_gemmU(const float* __restrict__ x,
                         const float* __restrict__ U_w,
                         const float* __restrict__ U_b,
                         const float* __restrict__ ln_w,
                         const float* __restrict__ ln_b) {
    const int half = blockIdx.x;          // 0 -> xh cols, 1 -> z cols
    const int r0   = blockIdx.y * 8;
    const int j    = threadIdx.x;         // 0..383
    __shared__ float xs[8][FEAT];
    for (int i = j; i < 8 * FEAT; i += 384) {
        int r = i / FEAT, k = i % FEAT;
        xs[r][k] = x[(r0 + r) * FEAT + k];
    }
    __syncthreads();
    float acc[8];
    const float b = U_b[half * ZD + j];
#pragma unroll
    for (int r = 0; r < 8; r++) acc[r] = b;
    const float* wcol = U_w + half * ZD + j;
#pragma unroll 4
    for (int k = 0; k < FEAT; k++) {
        float w = wcol[(size_t)k * FFN];
#pragma unroll
        for (int r = 0; r < 8; r++) acc[r] += xs[r][k] * w;
    }
    float v[8];
#pragma unroll
    for (int r = 0; r < 8; r++) v[r] = gelu_exact(acc[r]);

    if (half == 0) {
#pragma unroll
        for (int r = 0; r < 8; r++) g_xh[(r0 + r) * ZD + j] = v[r];
        return;
    }
    // ---- fused LayerNorm for the z half: this block owns full rows ----
    __shared__ float rs1[8][12], rs2[8][12];
    __shared__ float mu_s[8], rsd_s[8];
    const int w = j >> 5, l = j & 31;
#pragma unroll
    for (int r = 0; r < 8; r++) {
        float s = v[r], q = v[r] * v[r];
#pragma unroll
        for (int o = 16; o > 0; o >>= 1) {
            s += __shfl_down_sync(0xffffffffu, s, o);
            q += __shfl_down_sync(0xffffffffu, q, o);
        }
        if (l == 0) { rs1[r][w] = s; rs2[r][w] = q; }
    }
    __syncthreads();
    if (j < 8) {
        float s = 0.f, q = 0.f;
#pragma unroll
        for (int i = 0; i < 12; i++) { s += rs1[j][i]; q += rs2[j][i]; }
        float mu  = s * (1.0f / ZD);
        float var = q * (1.0f / ZD) - mu * mu;
        mu_s[j]  = mu;
        rsd_s[j] = rsqrtf(var + LN_EPS);
    }
    __syncthreads();
    const float lw = ln_w[j], lb = ln_b[j];
#pragma unroll
    for (int r = 0; r < 8; r++)
        g_z[(r0 + r) * ZD + j] = (v[r] - mu_s[r]) * rsd_s[r] * lw + lb;
}

// ---------------- k2: AE on diagonal + both dot products (4-row tiles) ----
// grid 128 blocks, block 384 threads.
// enc GEMM: k-split 2-way across block, 4 rows/thread (4 FMA per load)
// dec GEMM: 1 col/thread, 4 rows (4 FMA per load)
__global__ void k2_ae(const float* __restrict__ enc_w,
                      const float* __restrict__ enc_b,
                      const float* __restrict__ dec_w,
                      const float* __restrict__ dec_b) {
    const int r0 = blockIdx.x * 4;
    const int t  = threadIdx.x;           // 0..383 (12 warps)
    __shared__ float zs[4][ZD];           // 6 KB
    __shared__ float hp[2][4][HID];       // 6 KB  enc partials
    __shared__ float hs[4][HID];          // 3 KB  gelu'd hidden
    __shared__ float redd[4][12], redo[4][12];

    // stage z tile (coalesced: 4 contiguous 384-float chunks)
    const float* zg = g_z + (size_t)r0 * ZD;
#pragma unroll
    for (int i = 0; i < 4; i++) {
        int idx = t + i * 384;
        zs[i][t] = zg[idx];               // idx = i*384 + t, row i col t
    }
    __syncthreads();

    // ---- encoder GEMM, k-split ----
    const int c  = t % HID;               // hidden column 0..191
    const int kq = t / HID;               // k half 0/1
    float a0 = 0.f, a1 = 0.f, a2 = 0.f, a3 = 0.f;
    const float* wp  = enc_w + (size_t)(kq * 192) * HID + c;
    const float* zp0 = &zs[0][kq * 192];
    const float* zp1 = &zs[1][kq * 192];
    const float* zp2 = &zs[2][kq * 192];
    const float* zp3 = &zs[3][kq * 192];
#pragma unroll 8
    for (int k = 0; k < 192; k++) {
        float w = wp[(size_t)k * HID];
        a0 += zp0[k] * w;
        a1 += zp1[k] * w;
        a2 += zp2[k] * w;
        a3 += zp3[k] * w;
    }
    hp[kq][0][c] = a0; hp[kq][1][c] = a1;
    hp[kq][2][c] = a2; hp[kq][3][c] = a3;
    __syncthreads();
    if (kq == 0) {
        float eb = enc_b[c];
#pragma unroll
        for (int r = 0; r < 4; r++)
            hs[r][c] = gelu_exact(hp[0][r][c] + hp[1][r][c] + eb);
    }
    __syncthreads();

    // ---- decoder GEMM + dots ----
    const int f = t;                      // 0..383
    float vb = dec_b[f];
    float p0 = vb, p1 = vb, p2 = vb, p3 = vb;
#pragma unroll 8
    for (int u = 0; u < HID; u++) {
        float w = dec_w[(size_t)u * ZD + f];
        p0 += hs[0][u] * w;
        p1 += hs[1][u] * w;
        p2 += hs[2][u] * w;
        p3 += hs[3][u] * w;
    }
    const float c0f = g_c0[f];
    float d[4], o[4];
    d[0] = p0 * zs[0][f]; d[1] = p1 * zs[1][f];
    d[2] = p2 * zs[2][f]; d[3] = p3 * zs[3][f];
    o[0] = c0f * zs[0][f]; o[1] = c0f * zs[1][f];
    o[2] = c0f * zs[2][f]; o[3] = c0f * zs[3][f];

    const int w = t >> 5, l = t & 31;
#pragma unroll
    for (int r = 0; r < 4; r++) {
        float dd = d[r], oo = o[r];
#pragma unroll
        for (int s = 16; s > 0; s >>= 1) {
            dd += __shfl_down_sync(0xffffffffu, dd, s);
            oo += __shfl_down_sync(0xffffffffu, oo, s);
        }
        if (l == 0) { redd[r][w] = dd; redo[r][w] = oo; }
    }
    __syncthreads();
    if (t < 4) {
        float dd = 0.f, oo = 0.f;
#pragma unroll
        for (int i = 0; i < 12; i++) { dd += redd[t][i]; oo += redo[t][i]; }
        g_diag[r0 + t] = dd;
        g_off[r0 + t]  = oo;
    }
}

// ---------------- k3: per-batch softmax stats + T aggregation -------------
// grid 4 blocks (one per batch), block 384
__global__ void k3_softmax() {
    const int b = blockIdx.x;
    const int t = threadIdx.x;            // 0..383
    __shared__ float eo[NN], ed[NN];
    __shared__ float red[13];
    float off = -1e30f, dg = -1e30f;
    if (t < NN) { off = g_off[b * NN + t]; dg = g_diag[b * NN + t]; }
    float m = fmaxf(off, dg);
#pragma unroll
    for (int o = 16; o > 0; o >>= 1) m = fmaxf(m, __shfl_down_sync(0xffffffffu, m, o));
    int w = t >> 5, l = t & 31;
    if (l == 0) red[w] = m;
    __syncthreads();
    if (t == 0) {
        float mm = -1e30f;
#pragma unroll
        for (int i = 0; i < 12; i++) mm = fmaxf(mm, red[i]);
        red[12] = mm;
    }
    __syncthreads();
    m = red[12];
    float e1 = 0.f;
    if (t < NN) {
        float a = expf(off - m), c = expf(dg - m);
        eo[t] = a; ed[t] = c;
        e1 = a;
    }
    __syncthreads();
#pragma unroll
    for (int o = 16; o > 0; o >>= 1) e1 += __shfl_down_sync(0xffffffffu, e1, o);
    if (l == 0) red[w] = e1;
    __syncthreads();
    if (t == 0) {
        float s = 0.f;
#pragma unroll
        for (int i = 0; i < 12; i++) s += red[i];
        red[12] = s;
    }
    __syncthreads();
    const float S = red[12];
    if (t < NN) {
        float a = eo[t], c = ed[t];
        g_wd[b * NN + t] = c - a;
        g_rD[b * NN + t] = 1.0f / (S - a + c);
    }
    // T[f] = sum_j e_off[j] * xh[b,j,f]
    float acc = 0.f;
    const float* xh = g_xh + (size_t)b * NN * ZD + t;
#pragma unroll 4
    for (int j = 0; j < NN; j++) acc += eo[j] * xh[(size_t)j * ZD];
    g_T[b * ZD + t] = acc;
}

// ---------------- k4: combine + final GEMM (out = u @ V_w + V_b) ----------
// grid 128 blocks (4 rows each), block 384
__global__ void k4_out(const float* __restrict__ V_w,
                       const float* __restrict__ V_b,
                       float* __restrict__ out) {
    const int r0 = blockIdx.x * 4;
    const int g  = threadIdx.x;           // 0..383
    const int b  = r0 / NN;               // 4 rows never straddle a batch
    __shared__ float us[4][ZD];
#pragma unroll
    for (int r = 0; r < 4; r++) {
        int row = r0 + r;
        us[r][g] = (g_T[b * ZD + g] + g_wd[row] * g_xh[row * ZD + g]) * g_rD[row];
    }
    __syncthreads();
    float acc[4];
    const float vb = V_b[g];
#pragma unroll
    for (int r = 0; r < 4; r++) acc[r] = vb;
    const float* wc = V_w + g;
#pragma unroll 8
    for (int f = 0; f < ZD; f++) {
        float w = wc[(size_t)f * FEAT];
#pragma unroll
        for (int r = 0; r < 4; r++) acc[r] += us[r][f] * w;
    }
#pragma unroll
    for (int r = 0; r < 4; r++) out[(r0 + r) * FEAT + g] = acc[r];
}

// ---------------- launch ---------------------------------------------------
extern "C" void kernel_launch(void* const* d_in, const int* in_sizes, int n_in,
                              void* d_out, int out_size) {
    const float* x     = (const float*)d_in[0];
    const float* U_w   = (const float*)d_in[1];
    const float* U_b   = (const float*)d_in[2];
    const float* ln_w  = (const float*)d_in[3];
    const float* ln_b  = (const float*)d_in[4];
    const float* enc_w = (const float*)d_in[5];
    const float* enc_b = (const float*)d_in[6];
    const float* dec_w = (const float*)d_in[7];
    const float* dec_b = (const float*)d_in[8];
    const float* V_w   = (const float*)d_in[9];
    const float* V_b   = (const float*)d_in[10];
    float* out = (float*)d_out;

    k0_c0<<<1, 384>>>(enc_b, dec_w, dec_b);
    dim3 g1(2, 64);
    k1_gemmU<<<g1, 384>>>(x, U_w, U_b, ln_w, ln_b);
    k2_ae<<<NN, 384>>>(enc_w, enc_b, dec_w, dec_b);
    k3_softmax<<<NB, 384>>>();
    k4_out<<<NN, 384>>>(V_w, V_b, out);
}

// round 5
// speedup vs baseline: 1.2489x; 1.1243x over previous
#include <cuda_runtime.h>
#include <math.h>

#define BN   512     // B*N
#define FEAT 384
#define FFN  768
#define ZD   384
#define HID  192
#define NB   4
#define NN   128
#define LN_EPS 1e-5f

// ---------------- scratch (device globals; no allocation) ----------------
__device__ float g_xh[BN * ZD];     // gelu'd first half
__device__ float g_z[BN * ZD];      // LN'd second half
__device__ float g_c0[ZD];          // gelu(enc_b) @ dec_w + dec_b
__device__ float g_diag[BN];
__device__ float g_off[BN];
__device__ float g_eo[BN];          // e_off (post max-shift)
__device__ float g_wd[BN];          // e_diag - e_off
__device__ float g_rD[BN];          // 1 / (S - e_off + e_diag)

__device__ __forceinline__ float gelu_exact(float x) {
    return 0.5f * x * (1.0f + erff(x * 0.70710678118654752440f));
}

// ---------------- k1: h = gelu(x @ U_w + U_b); xh half / z half (+LN) -----
// 1D grid of 129 blocks, block 384.
//   bid < 128 : GEMM tile — half = bid & 1, row-group = bid >> 1 (8 rows)
//   bid == 128: c0 = gelu(enc_b) @ dec_w + dec_b
__global__ void k1_gemmU(const float* __restrict__ x,
                         const float* __restrict__ U_w,
                         const float* __restrict__ U_b,
                         const float* __restrict__ ln_w,
                         const float* __restrict__ ln_b,
                         const float* __restrict__ enc_b,
                         const float* __restrict__ dec_w,
                         const float* __restrict__ dec_b) {
    const int j = threadIdx.x;            // 0..383
    if (blockIdx.x == 128) {
        __shared__ float gh[HID];
        if (j < HID) gh[j] = gelu_exact(enc_b[j]);
        __syncthreads();
        float acc = dec_b[j];
#pragma unroll 8
        for (int u = 0; u < HID; u++) acc += gh[u] * dec_w[u * ZD + j];
        g_c0[j] = acc;
        return;
    }
    const int half = blockIdx.x & 1;      // 0 -> xh cols, 1 -> z cols
    const int r0   = (blockIdx.x >> 1) * 8;
    __shared__ float xs[8][FEAT];
    for (int i = j; i < 8 * FEAT; i += 384) {
        int r = i / FEAT, k = i % FEAT;
        xs[r][k] = x[(r0 + r) * FEAT + k];
    }
    __syncthreads();
    float acc[8];
    const float b = U_b[half * ZD + j];
#pragma unroll
    for (int r = 0; r < 8; r++) acc[r] = b;
    const float* wcol = U_w + half * ZD + j;
#pragma unroll 8
    for (int k = 0; k < FEAT; k++) {
        float w = wcol[(size_t)k * FFN];
#pragma unroll
        for (int r = 0; r < 8; r++) acc[r] += xs[r][k] * w;
    }
    float v[8];
#pragma unroll
    for (int r = 0; r < 8; r++) v[r] = gelu_exact(acc[r]);

    if (half == 0) {
#pragma unroll
        for (int r = 0; r < 8; r++) g_xh[(r0 + r) * ZD + j] = v[r];
        return;
    }
    // ---- fused LayerNorm for the z half: this block owns full rows ----
    __shared__ float rs1[8][12], rs2[8][12];
    __shared__ float mu_s[8], rsd_s[8];
    const int w = j >> 5, l = j & 31;
#pragma unroll
    for (int r = 0; r < 8; r++) {
        float s = v[r], q = v[r] * v[r];
#pragma unroll
        for (int o = 16; o > 0; o >>= 1) {
            s += __shfl_down_sync(0xffffffffu, s, o);
            q += __shfl_down_sync(0xffffffffu, q, o);
        }
        if (l == 0) { rs1[r][w] = s; rs2[r][w] = q; }
    }
    __syncthreads();
    if (j < 8) {
        float s = 0.f, q = 0.f;
#pragma unroll
        for (int i = 0; i < 12; i++) { s += rs1[j][i]; q += rs2[j][i]; }
        float mu  = s * (1.0f / ZD);
        float var = q * (1.0f / ZD) - mu * mu;
        mu_s[j]  = mu;
        rsd_s[j] = rsqrtf(var + LN_EPS);
    }
    __syncthreads();
    const float lw = ln_w[j], lb = ln_b[j];
#pragma unroll
    for (int r = 0; r < 8; r++)
        g_z[(r0 + r) * ZD + j] = (v[r] - mu_s[r]) * rsd_s[r] * lw + lb;
}

// ---------------- k2: AE on diagonal + both dot products (4-row tiles) ----
__global__ void k2_ae(const float* __restrict__ enc_w,
                      const float* __restrict__ enc_b,
                      const float* __restrict__ dec_w,
                      const float* __restrict__ dec_b) {
    const int r0 = blockIdx.x * 4;
    const int t  = threadIdx.x;           // 0..383 (12 warps)
    __shared__ float zs[4][ZD];
    __shared__ float hp[2][4][HID];
    __shared__ float hs[4][HID];
    __shared__ float redd[4][12], redo[4][12];

    const float* zg = g_z + (size_t)r0 * ZD;
#pragma unroll
    for (int i = 0; i < 4; i++) zs[i][t] = zg[t + i * 384];
    __syncthreads();

    // ---- encoder GEMM, k-split 2-way ----
    const int c  = t % HID;
    const int kq = t / HID;
    float a0 = 0.f, a1 = 0.f, a2 = 0.f, a3 = 0.f;
    const float* wp  = enc_w + (size_t)(kq * 192) * HID + c;
    const float* zp0 = &zs[0][kq * 192];
    const float* zp1 = &zs[1][kq * 192];
    const float* zp2 = &zs[2][kq * 192];
    const float* zp3 = &zs[3][kq * 192];
#pragma unroll 8
    for (int k = 0; k < 192; k++) {
        float w = wp[(size_t)k * HID];
        a0 += zp0[k] * w;
        a1 += zp1[k] * w;
        a2 += zp2[k] * w;
        a3 += zp3[k] * w;
    }
    hp[kq][0][c] = a0; hp[kq][1][c] = a1;
    hp[kq][2][c] = a2; hp[kq][3][c] = a3;
    __syncthreads();
    if (kq == 0) {
        float eb = enc_b[c];
#pragma unroll
        for (int r = 0; r < 4; r++)
            hs[r][c] = gelu_exact(hp[0][r][c] + hp[1][r][c] + eb);
    }
    __syncthreads();

    // ---- decoder GEMM + dots ----
    const int f = t;
    float vb = dec_b[f];
    float p0 = vb, p1 = vb, p2 = vb, p3 = vb;
#pragma unroll 8
    for (int u = 0; u < HID; u++) {
        float w = dec_w[(size_t)u * ZD + f];
        p0 += hs[0][u] * w;
        p1 += hs[1][u] * w;
        p2 += hs[2][u] * w;
        p3 += hs[3][u] * w;
    }
    const float c0f = g_c0[f];
    float d[4], o[4];
    d[0] = p0 * zs[0][f]; d[1] = p1 * zs[1][f];
    d[2] = p2 * zs[2][f]; d[3] = p3 * zs[3][f];
    o[0] = c0f * zs[0][f]; o[1] = c0f * zs[1][f];
    o[2] = c0f * zs[2][f]; o[3] = c0f * zs[3][f];

    const int w = t >> 5, l = t & 31;
#pragma unroll
    for (int r = 0; r < 4; r++) {
        float dd = d[r], oo = o[r];
#pragma unroll
        for (int s = 16; s > 0; s >>= 1) {
            dd += __shfl_down_sync(0xffffffffu, dd, s);
            oo += __shfl_down_sync(0xffffffffu, oo, s);
        }
        if (l == 0) { redd[r][w] = dd; redo[r][w] = oo; }
    }
    __syncthreads();
    if (t < 4) {
        float dd = 0.f, oo = 0.f;
#pragma unroll
        for (int i = 0; i < 12; i++) { dd += redd[t][i]; oo += redo[t][i]; }
        g_diag[r0 + t] = dd;
        g_off[r0 + t]  = oo;
    }
}

// ---------------- k3: softmax stats only (4 blocks x 128 threads) ---------
__global__ void k3_stats() {
    const int b = blockIdx.x;
    const int t = threadIdx.x;            // 0..127 (4 warps)
    __shared__ float red[5];
    float off = g_off[b * NN + t];
    float dg  = g_diag[b * NN + t];
    float m = fmaxf(off, dg);
#pragma unroll
    for (int o = 16; o > 0; o >>= 1) m = fmaxf(m, __shfl_down_sync(0xffffffffu, m, o));
    const int w = t >> 5, l = t & 31;
    if (l == 0) red[w] = m;
    __syncthreads();
    if (t == 0) red[4] = fmaxf(fmaxf(red[0], red[1]), fmaxf(red[2], red[3]));
    __syncthreads();
    m = red[4];
    float a = expf(off - m), c = expf(dg - m);
    float e1 = a;
#pragma unroll
    for (int o = 16; o > 0; o >>= 1) e1 += __shfl_down_sync(0xffffffffu, e1, o);
    if (l == 0) red[w] = e1;
    __syncthreads();
    if (t == 0) red[4] = red[0] + red[1] + red[2] + red[3];
    __syncthreads();
    const float S = red[4];
    g_eo[b * NN + t] = a;
    g_wd[b * NN + t] = c - a;
    g_rD[b * NN + t] = 1.0f / (S - a + c);
}

// ---------------- k4: T on-the-fly + combine + final GEMM -----------------
// grid 128 blocks (4 rows each), block 384
__global__ void k4_out(const float* __restrict__ V_w,
                       const float* __restrict__ V_b,
                       float* __restrict__ out) {
    const int r0 = blockIdx.x * 4;
    const int g  = threadIdx.x;           // 0..383
    const int b  = r0 / NN;               // 4 rows never straddle a batch
    __shared__ float eo[NN];
    __shared__ float us[4][ZD];
    __shared__ float wd[4], rd[4];
    if (g < NN) eo[g] = g_eo[b * NN + g];
    if (g >= 376) {                       // lane-disjoint from eo loaders
        int r = g - 376;
        if (r < 4) { wd[r] = g_wd[r0 + r]; rd[r] = g_rD[r0 + r]; }
    }
    __syncthreads();
    // T[g] = sum_j eo[j] * xh[b,j,g]
    float T = 0.f;
    const float* xh = g_xh + (size_t)b * NN * ZD + g;
#pragma unroll 8
    for (int j = 0; j < NN; j++) T += eo[j] * xh[(size_t)j * ZD];
#pragma unroll
    for (int r = 0; r < 4; r++)
        us[r][g] = (T + wd[r] * g_xh[(r0 + r) * ZD + g]) * rd[r];
    __syncthreads();
    float acc[4];
    const float vb = V_b[g];
#pragma unroll
    for (int r = 0; r < 4; r++) acc[r] = vb;
    const float* wc = V_w + g;
#pragma unroll 8
    for (int f = 0; f < ZD; f++) {
        float w = wc[(size_t)f * FEAT];
#pragma unroll
        for (int r = 0; r < 4; r++) acc[r] += us[r][f] * w;
    }
#pragma unroll
    for (int r = 0; r < 4; r++) out[(r0 + r) * FEAT + g] = acc[r];
}

// ---------------- launch ---------------------------------------------------
extern "C" void kernel_launch(void* const* d_in, const int* in_sizes, int n_in,
                              void* d_out, int out_size) {
    const float* x     = (const float*)d_in[0];
    const float* U_w   = (const float*)d_in[1];
    const float* U_b   = (const float*)d_in[2];
    const float* ln_w  = (const float*)d_in[3];
    const float* ln_b  = (const float*)d_in[4];
    const float* enc_w = (const float*)d_in[5];
    const float* enc_b = (const float*)d_in[6];
    const float* dec_w = (const float*)d_in[7];
    const float* dec_b = (const float*)d_in[8];
    const float* V_w   = (const float*)d_in[9];
    const float* V_b   = (const float*)d_in[10];
    float* out = (float*)d_out;

    k1_gemmU<<<129, 384>>>(x, U_w, U_b, ln_w, ln_b, enc_b, dec_w, dec_b);
    k2_ae<<<NN, 384>>>(enc_w, enc_b, dec_w, dec_b);
    k3_stats<<<NB, NN>>>();
    k4_out<<<NN, 384>>>(V_w, V_b, out);
}

// round 6
// speedup vs baseline: 1.5056x; 1.2055x over previous
#include <cuda_runtime.h>
#include <math.h>

#define BN   512     // B*N
#define FEAT 384
#define FFN  768
#define ZD   384
#define HID  192
#define NB   4
#define NN   128
#define LN_EPS 1e-5f

// ---------------- scratch (device globals; no allocation) ----------------
__device__ __align__(16) float g_xh[BN * ZD];   // gelu'd first half
__device__ __align__(16) float g_z[BN * ZD];    // LN'd second half
__device__ __align__(16) float g_c0[ZD];        // gelu(enc_b) @ dec_w + dec_b
__device__ float g_diag[BN];
__device__ float g_off[BN];
__device__ float g_eo[BN];          // e_off (post max-shift)
__device__ float g_wd[BN];          // e_diag - e_off
__device__ float g_rD[BN];          // 1 / (S - e_off + e_diag)

__device__ __forceinline__ float gelu_exact(float x) {
    return 0.5f * x * (1.0f + erff(x * 0.70710678118654752440f));
}

// ---------------- k1: h = gelu(x @ U_w + U_b); xh half / z half (+LN) -----
// grid 129, block 384.
//   bid < 128 : half = bid&1, row-group = bid>>1 (8 rows), 384 out cols.
//               thread layout: cg = t%96 (4 cols), rg=(t/96)&1 (4 rows), kq=t/192 (192 k)
//   bid == 128: c0 = gelu(enc_b) @ dec_w + dec_b
__global__ void k1_gemmU(const float* __restrict__ x,
                         const float* __restrict__ U_w,
                         const float* __restrict__ U_b,
                         const float* __restrict__ ln_w,
                         const float* __restrict__ ln_b,
                         const float* __restrict__ enc_b,
                         const float* __restrict__ dec_w,
                         const float* __restrict__ dec_b) {
    const int t = threadIdx.x;            // 0..383
    if (blockIdx.x == 128) {
        __shared__ float gh[HID];
        if (t < HID) gh[t] = gelu_exact(enc_b[t]);
        __syncthreads();
        float acc = dec_b[t];
#pragma unroll 8
        for (int u = 0; u < HID; u++) acc += gh[u] * dec_w[u * ZD + t];
        g_c0[t] = acc;
        return;
    }
    const int half = blockIdx.x & 1;      // 0 -> xh cols, 1 -> z cols
    const int r0   = (blockIdx.x >> 1) * 8;

    __shared__ float xs[8][FEAT];         // 12 KB
    __shared__ float par[2][8][ZD];       // 24 KB  (kq partials)

    // stage x tile with float4 (768 float4s, 2 per thread)
#pragma unroll
    for (int i = 0; i < 2; i++) {
        int f4 = t + i * 384;
        int r = f4 / 96, kk = (f4 % 96) * 4;
        *(float4*)&xs[r][kk] = *(const float4*)(x + (size_t)(r0 + r) * FEAT + kk);
    }
    __syncthreads();

    const int cg = t % 96;                // output cols 4*cg .. 4*cg+3
    const int rg = (t / 96) & 1;          // rows rg*4 .. rg*4+3
    const int kq = t / 192;               // k range [kq*192, kq*192+192)
    const int c0c = 4 * cg;

    float a[4][4];
#pragma unroll
    for (int r = 0; r < 4; r++)
#pragma unroll
        for (int c = 0; c < 4; c++) a[r][c] = 0.f;

    const float* wbase = U_w + (size_t)kq * 192 * FFN + half * ZD + c0c;
    const float* xrow  = &xs[rg * 4][0];
#pragma unroll 4
    for (int k = 0; k < 192; k++) {
        float4 w = *(const float4*)(wbase + (size_t)k * FFN);
        int kk = kq * 192 + k;
#pragma unroll
        for (int r = 0; r < 4; r++) {
            float xv = xs[rg * 4 + r][kk];
            a[r][0] += xv * w.x; a[r][1] += xv * w.y;
            a[r][2] += xv * w.z; a[r][3] += xv * w.w;
        }
    }
#pragma unroll
    for (int r = 0; r < 4; r++)
        *(float4*)&par[kq][rg * 4 + r][c0c] = make_float4(a[r][0], a[r][1], a[r][2], a[r][3]);
    __syncthreads();

    // thread t = output col j; 8 rows
    const int j = t;
    const float b = U_b[half * ZD + j];
    float v[8];
#pragma unroll
    for (int r = 0; r < 8; r++)
        v[r] = gelu_exact(par[0][r][j] + par[1][r][j] + b);

    if (half == 0) {
#pragma unroll
        for (int r = 0; r < 8; r++) g_xh[(r0 + r) * ZD + j] = v[r];
        return;
    }
    // ---- fused LayerNorm for the z half ----
    __shared__ float rs1[8][12], rs2[8][12];
    __shared__ float mu_s[8], rsd_s[8];
    const int w = j >> 5, l = j & 31;
#pragma unroll
    for (int r = 0; r < 8; r++) {
        float s = v[r], q = v[r] * v[r];
#pragma unroll
        for (int o = 16; o > 0; o >>= 1) {
            s += __shfl_down_sync(0xffffffffu, s, o);
            q += __shfl_down_sync(0xffffffffu, q, o);
        }
        if (l == 0) { rs1[r][w] = s; rs2[r][w] = q; }
    }
    __syncthreads();
    if (j < 8) {
        float s = 0.f, q = 0.f;
#pragma unroll
        for (int i = 0; i < 12; i++) { s += rs1[j][i]; q += rs2[j][i]; }
        float mu  = s * (1.0f / ZD);
        float var = q * (1.0f / ZD) - mu * mu;
        mu_s[j]  = mu;
        rsd_s[j] = rsqrtf(var + LN_EPS);
    }
    __syncthreads();
    const float lw = ln_w[j], lb = ln_b[j];
#pragma unroll
    for (int r = 0; r < 8; r++)
        g_z[(r0 + r) * ZD + j] = (v[r] - mu_s[r]) * rsd_s[r] * lw + lb;
}

// ---------------- k2: AE on diagonal + both dot products (4-row tiles) ----
// grid 128 blocks, block 384 threads.
#define ZP (ZD + 4)
__global__ void k2_ae(const float* __restrict__ enc_w,
                      const float* __restrict__ enc_b,
                      const float* __restrict__ dec_w,
                      const float* __restrict__ dec_b) {
    const int r0 = blockIdx.x * 4;
    const int t  = threadIdx.x;           // 0..383 (12 warps)
    __shared__ float zs[4][ZP];           // padded: mixed-rg warps conflict-free
    __shared__ float hs[4][HID];
    __shared__ float par[3072];           // 12 KB, reused enc->dec
    __shared__ float redd[4][12], redo[4][12];

    // stage z tile (float4: 384 loads, 1/thread)
    {
        int r = t / 96, kk = (t % 96) * 4;
        *(float4*)&zs[r][kk] = *(const float4*)(g_z + (size_t)(r0 + r) * ZD + kk);
    }
    __syncthreads();

    // ---- encoder GEMM: cg2=t%48 (4 cols), rg=(t/48)&1 (2 rows), kq=t/96 (96 k)
    {
        const int cg2 = t % 48;
        const int rg  = (t / 48) & 1;
        const int kq  = t / 96;
        const int cc  = 4 * cg2;
        float a[2][4];
#pragma unroll
        for (int r = 0; r < 2; r++)
#pragma unroll
            for (int c = 0; c < 4; c++) a[r][c] = 0.f;
        const float* wbase = enc_w + (size_t)kq * 96 * HID + cc;
#pragma unroll 4
        for (int k = 0; k < 96; k++) {
            float4 w = *(const float4*)(wbase + (size_t)k * HID);
            int kk = kq * 96 + k;
#pragma unroll
            for (int r = 0; r < 2; r++) {
                float zv = zs[rg * 2 + r][kk];
                a[r][0] += zv * w.x; a[r][1] += zv * w.y;
                a[r][2] += zv * w.z; a[r][3] += zv * w.w;
            }
        }
        // par layout: [kq][row][col] = kq*768 + r*192 + c
#pragma unroll
        for (int r = 0; r < 2; r++)
            *(float4*)&par[kq * 768 + (rg * 2 + r) * HID + cc] =
                make_float4(a[r][0], a[r][1], a[r][2], a[r][3]);
    }
    __syncthreads();
    // reduce 4 kq partials -> hs (768 entries, 2/thread)
#pragma unroll
    for (int i = 0; i < 2; i++) {
        int idx = t + i * 384;
        int r = idx / HID, c = idx % HID;
        float h = par[r * HID + c] + par[768 + r * HID + c]
                + par[1536 + r * HID + c] + par[2304 + r * HID + c] + enc_b[c];
        hs[r][c] = gelu_exact(h);
    }
    __syncthreads();

    // ---- decoder GEMM: cg=t%96 (4 cols), rg=(t/96)&1 (2 rows), kq=t/192 (96 u)
    {
        const int cg = t % 96;
        const int rg = (t / 96) & 1;
        const int kq = t / 192;
        const int cc = 4 * cg;
        float a[2][4];
#pragma unroll
        for (int r = 0; r < 2; r++)
#pragma unroll
            for (int c = 0; c < 4; c++) a[r][c] = 0.f;
        const float* wbase = dec_w + (size_t)kq * 96 * ZD + cc;
#pragma unroll 4
        for (int u = 0; u < 96; u++) {
            float4 w = *(const float4*)(wbase + (size_t)u * ZD);
            int uu = kq * 96 + u;
#pragma unroll
            for (int r = 0; r < 2; r++) {
                float hv = hs[rg * 2 + r][uu];
                a[r][0] += hv * w.x; a[r][1] += hv * w.y;
                a[r][2] += hv * w.z; a[r][3] += hv * w.w;
            }
        }
        // par layout: [kq][row][col] = kq*1536 + r*384 + c
#pragma unroll
        for (int r = 0; r < 2; r++)
            *(float4*)&par[kq * 1536 + (rg * 2 + r) * ZD + cc] =
                make_float4(a[r][0], a[r][1], a[r][2], a[r][3]);
    }
    __syncthreads();

    // reduce + dots: thread t = col t, 4 rows
    const float db = dec_b[t];
    const float c0f = g_c0[t];
    float d[4], o[4];
#pragma unroll
    for (int r = 0; r < 4; r++) {
        float p = par[r * ZD + t] + par[1536 + r * ZD + t] + db;
        float zv = zs[r][t];
        d[r] = p * zv;
        o[r] = c0f * zv;
    }
    const int w = t >> 5, l = t & 31;
#pragma unroll
    for (int r = 0; r < 4; r++) {
        float dd = d[r], oo = o[r];
#pragma unroll
        for (int s = 16; s > 0; s >>= 1) {
            dd += __shfl_down_sync(0xffffffffu, dd, s);
            oo += __shfl_down_sync(0xffffffffu, oo, s);
        }
        if (l == 0) { redd[r][w] = dd; redo[r][w] = oo; }
    }
    __syncthreads();
    if (t < 4) {
        float dd = 0.f, oo = 0.f;
#pragma unroll
        for (int i = 0; i < 12; i++) { dd += redd[t][i]; oo += redo[t][i]; }
        g_diag[r0 + t] = dd;
        g_off[r0 + t]  = oo;
    }
}

// ---------------- k3: softmax stats only (4 blocks x 128 threads) ---------
__global__ void k3_stats() {
    const int b = blockIdx.x;
    const int t = threadIdx.x;            // 0..127 (4 warps)
    __shared__ float red[5];
    float off = g_off[b * NN + t];
    float dg  = g_diag[b * NN + t];
    float m = fmaxf(off, dg);
#pragma unroll
    for (int o = 16; o > 0; o >>= 1) m = fmaxf(m, __shfl_down_sync(0xffffffffu, m, o));
    const int w = t >> 5, l = t & 31;
    if (l == 0) red[w] = m;
    __syncthreads();
    if (t == 0) red[4] = fmaxf(fmaxf(red[0], red[1]), fmaxf(red[2], red[3]));
    __syncthreads();
    m = red[4];
    float a = expf(off - m), c = expf(dg - m);
    float e1 = a;
#pragma unroll
    for (int o = 16; o > 0; o >>= 1) e1 += __shfl_down_sync(0xffffffffu, e1, o);
    if (l == 0) red[w] = e1;
    __syncthreads();
    if (t == 0) red[4] = red[0] + red[1] + red[2] + red[3];
    __syncthreads();
    const float S = red[4];
    g_eo[b * NN + t] = a;
    g_wd[b * NN + t] = c - a;
    g_rD[b * NN + t] = 1.0f / (S - a + c);
}

// ---------------- k4: T on-the-fly + combine + final GEMM -----------------
// grid 128 blocks (4 rows each), block 384
__global__ void k4_out(const float* __restrict__ V_w,
                       const float* __restrict__ V_b,
                       float* __restrict__ out) {
    const int r0 = blockIdx.x * 4;
    const int t  = threadIdx.x;           // 0..383
    const int b  = r0 / NN;               // 4 rows never straddle a batch
    __shared__ float eo[NN];
    __shared__ float us[4][ZD];
    __shared__ float par[3072];           // [kq][row][col] 12 KB
    __shared__ float wd[4], rd[4];
    if (t < NN) eo[t] = g_eo[b * NN + t];
    if (t >= 376) {                       // lane-disjoint from eo loaders
        int r = t - 376;
        if (r < 4) { wd[r] = g_wd[r0 + r]; rd[r] = g_rD[r0 + r]; }
    }
    __syncthreads();
    // T[t] = sum_j eo[j] * xh[b,j,t]
    float T = 0.f;
    const float* xh = g_xh + (size_t)b * NN * ZD + t;
#pragma unroll 8
    for (int j = 0; j < NN; j++) T += eo[j] * xh[(size_t)j * ZD];
#pragma unroll
    for (int r = 0; r < 4; r++)
        us[r][t] = (T + wd[r] * g_xh[(r0 + r) * ZD + t]) * rd[r];
    __syncthreads();

    // GEMM: cg=t%96 (4 cols), rg=(t/96)&1 (2 rows), kq=t/192 (192 f)
    const int cg = t % 96;
    const int rg = (t / 96) & 1;
    const int kq = t / 192;
    const int cc = 4 * cg;
    float a[2][4];
#pragma unroll
    for (int r = 0; r < 2; r++)
#pragma unroll
        for (int c = 0; c < 4; c++) a[r][c] = 0.f;
    const float* wbase = V_w + (size_t)kq * 192 * FEAT + cc;
#pragma unroll 4
    for (int f = 0; f < 192; f++) {
        float4 w = *(const float4*)(wbase + (size_t)f * FEAT);
        int ff = kq * 192 + f;
#pragma unroll
        for (int r = 0; r < 2; r++) {
            float uv = us[rg * 2 + r][ff];
            a[r][0] += uv * w.x; a[r][1] += uv * w.y;
            a[r][2] += uv * w.z; a[r][3] += uv * w.w;
        }
    }
#pragma unroll
    for (int r = 0; r < 2; r++)
        *(float4*)&par[kq * 1536 + (rg * 2 + r) * FEAT + cc] =
            make_float4(a[r][0], a[r][1], a[r][2], a[r][3]);
    __syncthreads();

    const float vb = V_b[t];
#pragma unroll
    for (int r = 0; r < 4; r++)
        out[(r0 + r) * FEAT + t] = par[r * FEAT + t] + par[1536 + r * FEAT + t] + vb;
}

// ---------------- launch ---------------------------------------------------
extern "C" void kernel_launch(void* const* d_in, const int* in_sizes, int n_in,
                              void* d_out, int out_size) {
    const float* x     = (const float*)d_in[0];
    const float* U_w   = (const float*)d_in[1];
    const float* U_b   = (const float*)d_in[2];
    const float* ln_w  = (const float*)d_in[3];
    const float* ln_b  = (const float*)d_in[4];
    const float* enc_w = (const float*)d_in[5];
    const float* enc_b = (const float*)d_in[6];
    const float* dec_w = (const float*)d_in[7];
    const float* dec_b = (const float*)d_in[8];
    const float* V_w   = (const float*)d_in[9];
    const float* V_b   = (const float*)d_in[10];
    float* out = (float*)d_out;

    k1_gemmU<<<129, 384>>>(x, U_w, U_b, ln_w, ln_b, enc_b, dec_w, dec_b);
    k2_ae<<<NN, 384>>>(enc_w, enc_b, dec_w, dec_b);
    k3_stats<<<NB, NN>>>();
    k4_out<<<NN, 384>>>(V_w, V_b, out);
}

// round 7
// speedup vs baseline: 2.4834x; 1.6494x over previous
#include <cuda_runtime.h>
#include <math.h>

#define BN   512     // B*N
#define FEAT 384
#define FFN  768
#define ZD   384
#define HID  192
#define NB   4
#define NN   128
#define LN_EPS 1e-5f

// ---------------- scratch (device globals; no allocation) ----------------
__device__ __align__(16) float g_xh[BN * ZD];   // gelu'd first half
__device__ __align__(16) float g_z[BN * ZD];    // LN'd second half
__device__ __align__(16) float g_c0[ZD];        // gelu(enc_b) @ dec_w + dec_b
__device__ float g_diag[BN];
__device__ float g_off[BN];
__device__ float g_eo[BN];          // e_off (post max-shift)
__device__ float g_wd[BN];          // e_diag - e_off
__device__ float g_rD[BN];          // 1 / (S - e_off + e_diag)

__device__ __forceinline__ float gelu_exact(float x) {
    return 0.5f * x * (1.0f + erff(x * 0.70710678118654752440f));
}

// ---------------- k1: h = gelu(x @ U_w + U_b); xh half / z half (+LN) -----
// grid 129, block 384.
__global__ __launch_bounds__(384, 1)
void k1_gemmU(const float* __restrict__ x,
              const float* __restrict__ U_w,
              const float* __restrict__ U_b,
              const float* __restrict__ ln_w,
              const float* __restrict__ ln_b,
              const float* __restrict__ enc_b,
              const float* __restrict__ dec_w,
              const float* __restrict__ dec_b) {
    const int t = threadIdx.x;            // 0..383
    if (blockIdx.x == 128) {
        __shared__ float gh[HID];
        if (t < HID) gh[t] = gelu_exact(enc_b[t]);
        __syncthreads();
        float acc = dec_b[t];
        for (int ub = 0; ub < HID; ub += 8) {
            float w[8];
#pragma unroll
            for (int i = 0; i < 8; i++) w[i] = dec_w[(ub + i) * ZD + t];
#pragma unroll
            for (int i = 0; i < 8; i++) acc += gh[ub + i] * w[i];
        }
        g_c0[t] = acc;
        return;
    }
    const int half = blockIdx.x & 1;      // 0 -> xh cols, 1 -> z cols
    const int r0   = (blockIdx.x >> 1) * 8;

    __shared__ float xs[8][FEAT];         // 12 KB
    __shared__ float par[2][8][ZD];       // 24 KB  (kq partials)

#pragma unroll
    for (int i = 0; i < 2; i++) {
        int f4 = t + i * 384;
        int r = f4 / 96, kk = (f4 % 96) * 4;
        *(float4*)&xs[r][kk] = *(const float4*)(x + (size_t)(r0 + r) * FEAT + kk);
    }
    __syncthreads();

    const int cg = t % 96;                // 4 output cols
    const int rg = (t / 96) & 1;          // 4 rows
    const int kq = t / 192;               // k half
    const int c0c = 4 * cg;

    float a[4][4];
#pragma unroll
    for (int r = 0; r < 4; r++)
#pragma unroll
        for (int c = 0; c < 4; c++) a[r][c] = 0.f;

    const float* wbase = U_w + (size_t)kq * 192 * FFN + half * ZD + c0c;
    for (int kb = 0; kb < 192; kb += 8) {
        float4 w[8];
#pragma unroll
        for (int i = 0; i < 8; i++)
            w[i] = *(const float4*)(wbase + (size_t)(kb + i) * FFN);
#pragma unroll
        for (int i = 0; i < 8; i++) {
            const int kk = kq * 192 + kb + i;
#pragma unroll
            for (int r = 0; r < 4; r++) {
                float xv = xs[rg * 4 + r][kk];
                a[r][0] += xv * w[i].x; a[r][1] += xv * w[i].y;
                a[r][2] += xv * w[i].z; a[r][3] += xv * w[i].w;
            }
        }
    }
#pragma unroll
    for (int r = 0; r < 4; r++)
        *(float4*)&par[kq][rg * 4 + r][c0c] = make_float4(a[r][0], a[r][1], a[r][2], a[r][3]);
    __syncthreads();

    const int j = t;
    const float b = U_b[half * ZD + j];
    float v[8];
#pragma unroll
    for (int r = 0; r < 8; r++)
        v[r] = gelu_exact(par[0][r][j] + par[1][r][j] + b);

    if (half == 0) {
#pragma unroll
        for (int r = 0; r < 8; r++) g_xh[(r0 + r) * ZD + j] = v[r];
        return;
    }
    // ---- fused LayerNorm for the z half ----
    __shared__ float rs1[8][12], rs2[8][12];
    __shared__ float mu_s[8], rsd_s[8];
    const int w = j >> 5, l = j & 31;
#pragma unroll
    for (int r = 0; r < 8; r++) {
        float s = v[r], q = v[r] * v[r];
#pragma unroll
        for (int o = 16; o > 0; o >>= 1) {
            s += __shfl_down_sync(0xffffffffu, s, o);
            q += __shfl_down_sync(0xffffffffu, q, o);
        }
        if (l == 0) { rs1[r][w] = s; rs2[r][w] = q; }
    }
    __syncthreads();
    if (j < 8) {
        float s = 0.f, q = 0.f;
#pragma unroll
        for (int i = 0; i < 12; i++) { s += rs1[j][i]; q += rs2[j][i]; }
        float mu  = s * (1.0f / ZD);
        float var = q * (1.0f / ZD) - mu * mu;
        mu_s[j]  = mu;
        rsd_s[j] = rsqrtf(var + LN_EPS);
    }
    __syncthreads();
    const float lw = ln_w[j], lb = ln_b[j];
#pragma unroll
    for (int r = 0; r < 8; r++)
        g_z[(r0 + r) * ZD + j] = (v[r] - mu_s[r]) * rsd_s[r] * lw + lb;
}

// ---------------- k2: AE on diagonal + both dot products (4-row tiles) ----
#define ZP (ZD + 4)
__global__ __launch_bounds__(384, 1)
void k2_ae(const float* __restrict__ enc_w,
           const float* __restrict__ enc_b,
           const float* __restrict__ dec_w,
           const float* __restrict__ dec_b) {
    const int r0 = blockIdx.x * 4;
    const int t  = threadIdx.x;           // 0..383 (12 warps)
    __shared__ float zs[4][ZP];
    __shared__ float hs[4][HID];
    __shared__ float par[3072];           // 12 KB, reused enc->dec
    __shared__ float redd[4][12], redo[4][12];

    {
        int r = t / 96, kk = (t % 96) * 4;
        *(float4*)&zs[r][kk] = *(const float4*)(g_z + (size_t)(r0 + r) * ZD + kk);
    }
    __syncthreads();

    // ---- encoder GEMM: cg2=t%48 (4 cols), rg=(t/48)&1 (2 rows), kq=t/96 (96 k)
    {
        const int cg2 = t % 48;
        const int rg  = (t / 48) & 1;
        const int kq  = t / 96;
        const int cc  = 4 * cg2;
        float a[2][4];
#pragma unroll
        for (int r = 0; r < 2; r++)
#pragma unroll
            for (int c = 0; c < 4; c++) a[r][c] = 0.f;
        const float* wbase = enc_w + (size_t)kq * 96 * HID + cc;
        for (int kb = 0; kb < 96; kb += 8) {
            float4 w[8];
#pragma unroll
            for (int i = 0; i < 8; i++)
                w[i] = *(const float4*)(wbase + (size_t)(kb + i) * HID);
#pragma unroll
            for (int i = 0; i < 8; i++) {
                const int kk = kq * 96 + kb + i;
#pragma unroll
                for (int r = 0; r < 2; r++) {
                    float zv = zs[rg * 2 + r][kk];
                    a[r][0] += zv * w[i].x; a[r][1] += zv * w[i].y;
                    a[r][2] += zv * w[i].z; a[r][3] += zv * w[i].w;
                }
            }
        }
#pragma unroll
        for (int r = 0; r < 2; r++)
            *(float4*)&par[kq * 768 + (rg * 2 + r) * HID + cc] =
                make_float4(a[r][0], a[r][1], a[r][2], a[r][3]);
    }
    __syncthreads();
#pragma unroll
    for (int i = 0; i < 2; i++) {
        int idx = t + i * 384;
        int r = idx / HID, c = idx % HID;
        float h = par[r * HID + c] + par[768 + r * HID + c]
                + par[1536 + r * HID + c] + par[2304 + r * HID + c] + enc_b[c];
        hs[r][c] = gelu_exact(h);
    }
    __syncthreads();

    // ---- decoder GEMM: cg=t%96 (4 cols), rg=(t/96)&1 (2 rows), kq=t/192 (96 u)
    {
        const int cg = t % 96;
        const int rg = (t / 96) & 1;
        const int kq = t / 192;
        const int cc = 4 * cg;
        float a[2][4];
#pragma unroll
        for (int r = 0; r < 2; r++)
#pragma unroll
            for (int c = 0; c < 4; c++) a[r][c] = 0.f;
        const float* wbase = dec_w + (size_t)kq * 96 * ZD + cc;
        for (int ub = 0; ub < 96; ub += 8) {
            float4 w[8];
#pragma unroll
            for (int i = 0; i < 8; i++)
                w[i] = *(const float4*)(wbase + (size_t)(ub + i) * ZD);
#pragma unroll
            for (int i = 0; i < 8; i++) {
                const int uu = kq * 96 + ub + i;
#pragma unroll
                for (int r = 0; r < 2; r++) {
                    float hv = hs[rg * 2 + r][uu];
                    a[r][0] += hv * w[i].x; a[r][1] += hv * w[i].y;
                    a[r][2] += hv * w[i].z; a[r][3] += hv * w[i].w;
                }
            }
        }
#pragma unroll
        for (int r = 0; r < 2; r++)
            *(float4*)&par[kq * 1536 + (rg * 2 + r) * ZD + cc] =
                make_float4(a[r][0], a[r][1], a[r][2], a[r][3]);
    }
    __syncthreads();

    const float db = dec_b[t];
    const float c0f = g_c0[t];
    float d[4], o[4];
#pragma unroll
    for (int r = 0; r < 4; r++) {
        float p = par[r * ZD + t] + par[1536 + r * ZD + t] + db;
        float zv = zs[r][t];
        d[r] = p * zv;
        o[r] = c0f * zv;
    }
    const int w = t >> 5, l = t & 31;
#pragma unroll
    for (int r = 0; r < 4; r++) {
        float dd = d[r], oo = o[r];
#pragma unroll
        for (int s = 16; s > 0; s >>= 1) {
            dd += __shfl_down_sync(0xffffffffu, dd, s);
            oo += __shfl_down_sync(0xffffffffu, oo, s);
        }
        if (l == 0) { redd[r][w] = dd; redo[r][w] = oo; }
    }
    __syncthreads();
    if (t < 4) {
        float dd = 0.f, oo = 0.f;
#pragma unroll
        for (int i = 0; i < 12; i++) { dd += redd[t][i]; oo += redo[t][i]; }
        g_diag[r0 + t] = dd;
        g_off[r0 + t]  = oo;
    }
}

// ---------------- k3: softmax stats only (4 blocks x 128 threads) ---------
__global__ void k3_stats() {
    const int b = blockIdx.x;
    const int t = threadIdx.x;            // 0..127 (4 warps)
    __shared__ float red[5];
    float off = g_off[b * NN + t];
    float dg  = g_diag[b * NN + t];
    float m = fmaxf(off, dg);
#pragma unroll
    for (int o = 16; o > 0; o >>= 1) m = fmaxf(m, __shfl_down_sync(0xffffffffu, m, o));
    const int w = t >> 5, l = t & 31;
    if (l == 0) red[w] = m;
    __syncthreads();
    if (t == 0) red[4] = fmaxf(fmaxf(red[0], red[1]), fmaxf(red[2], red[3]));
    __syncthreads();
    m = red[4];
    float a = expf(off - m), c = expf(dg - m);
    float e1 = a;
#pragma unroll
    for (int o = 16; o > 0; o >>= 1) e1 += __shfl_down_sync(0xffffffffu, e1, o);
    if (l == 0) red[w] = e1;
    __syncthreads();
    if (t == 0) red[4] = red[0] + red[1] + red[2] + red[3];
    __syncthreads();
    const float S = red[4];
    g_eo[b * NN + t] = a;
    g_wd[b * NN + t] = c - a;
    g_rD[b * NN + t] = 1.0f / (S - a + c);
}

// ---------------- k4: T on-the-fly + combine + final GEMM -----------------
__global__ __launch_bounds__(384, 1)
void k4_out(const float* __restrict__ V_w,
            const float* __restrict__ V_b,
            float* __restrict__ out) {
    const int r0 = blockIdx.x * 4;
    const int t  = threadIdx.x;           // 0..383
    const int b  = r0 / NN;               // 4 rows never straddle a batch
    __shared__ float eo[NN];
    __shared__ float us[4][ZD];
    __shared__ float par[3072];           // 12 KB
    __shared__ float wd[4], rd[4];
    if (t < NN) eo[t] = g_eo[b * NN + t];
    if (t >= 376) {
        int r = t - 376;
        if (r < 4) { wd[r] = g_wd[r0 + r]; rd[r] = g_rD[r0 + r]; }
    }
    __syncthreads();
    // T[t] = sum_j eo[j] * xh[b,j,t]  (batched 16-deep)
    float T = 0.f;
    const float* xh = g_xh + (size_t)b * NN * ZD + t;
    for (int jb = 0; jb < NN; jb += 16) {
        float xv[16];
#pragma unroll
        for (int i = 0; i < 16; i++) xv[i] = xh[(size_t)(jb + i) * ZD];
#pragma unroll
        for (int i = 0; i < 16; i++) T += eo[jb + i] * xv[i];
    }
#pragma unroll
    for (int r = 0; r < 4; r++)
        us[r][t] = (T + wd[r] * g_xh[(r0 + r) * ZD + t]) * rd[r];
    __syncthreads();

    // GEMM: cg=t%96 (4 cols), rg=(t/96)&1 (2 rows), kq=t/192 (192 f)
    const int cg = t % 96;
    const int rg = (t / 96) & 1;
    const int kq = t / 192;
    const int cc = 4 * cg;
    float a[2][4];
#pragma unroll
    for (int r = 0; r < 2; r++)
#pragma unroll
        for (int c = 0; c < 4; c++) a[r][c] = 0.f;
    const float* wbase = V_w + (size_t)kq * 192 * FEAT + cc;
    for (int fb = 0; fb < 192; fb += 8) {
        float4 w[8];
#pragma unroll
        for (int i = 0; i < 8; i++)
            w[i] = *(const float4*)(wbase + (size_t)(fb + i) * FEAT);
#pragma unroll
        for (int i = 0; i < 8; i++) {
            const int ff = kq * 192 + fb + i;
#pragma unroll
            for (int r = 0; r < 2; r++) {
                float uv = us[rg * 2 + r][ff];
                a[r][0] += uv * w[i].x; a[r][1] += uv * w[i].y;
                a[r][2] += uv * w[i].z; a[r][3] += uv * w[i].w;
            }
        }
    }
#pragma unroll
    for (int r = 0; r < 2; r++)
        *(float4*)&par[kq * 1536 + (rg * 2 + r) * FEAT + cc] =
            make_float4(a[r][0], a[r][1], a[r][2], a[r][3]);
    __syncthreads();

    const float vb = V_b[t];
#pragma unroll
    for (int r = 0; r < 4; r++)
        out[(r0 + r) * FEAT + t] = par[r * FEAT + t] + par[1536 + r * FEAT + t] + vb;
}

// ---------------- launch ---------------------------------------------------
extern "C" void kernel_launch(void* const* d_in, const int* in_sizes, int n_in,
                              void* d_out, int out_size) {
    const float* x     = (const float*)d_in[0];
    const float* U_w   = (const float*)d_in[1];
    const float* U_b   = (const float*)d_in[2];
    const float* ln_w  = (const float*)d_in[3];
    const float* ln_b  = (const float*)d_in[4];
    const float* enc_w = (const float*)d_in[5];
    const float* enc_b = (const float*)d_in[6];
    const float* dec_w = (const float*)d_in[7];
    const float* dec_b = (const float*)d_in[8];
    const float* V_w   = (const float*)d_in[9];
    const float* V_b   = (const float*)d_in[10];
    float* out = (float*)d_out;

    k1_gemmU<<<129, 384>>>(x, U_w, U_b, ln_w, ln_b, enc_b, dec_w, dec_b);
    k2_ae<<<NN, 384>>>(enc_w, enc_b, dec_w, dec_b);
    k3_stats<<<NB, NN>>>();
    k4_out<<<NN, 384>>>(V_w, V_b, out);
}

// round 8
// speedup vs baseline: 2.6125x; 1.0520x over previous
#include <cuda_runtime.h>
#include <math.h>

#define BN   512     // B*N
#define FEAT 384
#define FFN  768
#define ZD   384
#define HID  192
#define NB   4
#define NN   128
#define LN_EPS 1e-5f
#define XLD  388     // padded smem row stride (floats); 4*XLD*4B bank-offset != 0 mod 32

// ---------------- scratch (device globals; no allocation) ----------------
__device__ __align__(16) float g_xh[BN * ZD];   // gelu'd first half
__device__ __align__(16) float g_z[BN * ZD];    // RAW gelu second half (LN in k2)
__device__ __align__(16) float g_c0[ZD];        // gelu(enc_b) @ dec_w + dec_b
__device__ float g_diag[BN];
__device__ float g_off[BN];
__device__ float g_eo[BN];
__device__ float g_wd[BN];
__device__ float g_rD[BN];

__device__ __forceinline__ float gelu_exact(float x) {
    return 0.5f * x * (1.0f + erff(x * 0.70710678118654752440f));
}

// ---------------- k1: h = gelu(x @ U_w + U_b), tiled 16 rows x 96 cols ----
// grid 257: bid<256 -> ct=bid&7 (96-col tile of 768), rt=bid>>3 (16-row tile)
//           bid==256 -> c0 task
// threads 384: cg=t%24 (4 cols), rgrp=(t/24)&3 (4 rows), kq=t/96 (96 k each)
__global__ __launch_bounds__(384, 2)
void k1_gemmU(const float* __restrict__ x,
              const float* __restrict__ U_w,
              const float* __restrict__ U_b,
              const float* __restrict__ enc_b,
              const float* __restrict__ dec_w,
              const float* __restrict__ dec_b) {
    const int t = threadIdx.x;
    if (blockIdx.x == 256) {
        __shared__ float gh[HID];
        if (t < HID) gh[t] = gelu_exact(enc_b[t]);
        __syncthreads();
        float acc = dec_b[t];
        for (int ub = 0; ub < HID; ub += 8) {
            float w[8];
#pragma unroll
            for (int i = 0; i < 8; i++) w[i] = dec_w[(ub + i) * ZD + t];
#pragma unroll
            for (int i = 0; i < 8; i++) acc += gh[ub + i] * w[i];
        }
        g_c0[t] = acc;
        return;
    }
    const int ct  = blockIdx.x & 7;
    const int rt  = blockIdx.x >> 3;
    const int r0  = rt * 16;
    const int gc0 = ct * 96;

    __shared__ float sbuf[16 * XLD];      // xs, then reused as partials

    // stage x tile: 16 rows x 384 k (1536 float4s, 4 per thread)
#pragma unroll
    for (int i = 0; i < 4; i++) {
        int f4 = t + i * 384;
        int r = f4 / 96, kk = (f4 % 96) * 4;
        *(float4*)&sbuf[r * XLD + kk] = *(const float4*)(x + (size_t)(r0 + r) * FEAT + kk);
    }
    __syncthreads();

    const int cg   = t % 24;
    const int rgrp = (t / 24) & 3;
    const int kq   = t / 96;
    const int cc   = cg * 4;

    float acc[4][4];
#pragma unroll
    for (int r = 0; r < 4; r++)
#pragma unroll
        for (int c = 0; c < 4; c++) acc[r][c] = 0.f;

    const float* wb = U_w + (size_t)(kq * 96) * FFN + gc0 + cc;
    const float* xb = &sbuf[(rgrp * 4) * XLD + kq * 96];
    for (int kb = 0; kb < 96; kb += 4) {
        float4 w[4];
#pragma unroll
        for (int i = 0; i < 4; i++)
            w[i] = *(const float4*)(wb + (size_t)(kb + i) * FFN);
#pragma unroll
        for (int i = 0; i < 4; i++) {
#pragma unroll
            for (int r = 0; r < 4; r++) {
                float xv = xb[r * XLD + kb + i];
                acc[r][0] += xv * w[i].x; acc[r][1] += xv * w[i].y;
                acc[r][2] += xv * w[i].z; acc[r][3] += xv * w[i].w;
            }
        }
    }
    __syncthreads();   // all xs reads done; reuse sbuf for partials
#pragma unroll
    for (int r = 0; r < 4; r++)
        *(float4*)&sbuf[kq * 1536 + (rgrp * 4 + r) * 96 + cc] =
            make_float4(acc[r][0], acc[r][1], acc[r][2], acc[r][3]);
    __syncthreads();

    // reduce 4 kq partials + bias + gelu + store (4 outputs per thread)
#pragma unroll
    for (int i = 0; i < 4; i++) {
        int idx = t + i * 384;
        int r = idx / 96, c = idx % 96;
        float v = sbuf[r * 96 + c] + sbuf[1536 + r * 96 + c]
                + sbuf[3072 + r * 96 + c] + sbuf[4608 + r * 96 + c] + U_b[gc0 + c];
        v = gelu_exact(v);
        if (ct < 4) g_xh[(size_t)(r0 + r) * ZD + gc0 + c] = v;
        else        g_z[(size_t)(r0 + r) * ZD + (gc0 - 384) + c] = v;
    }
}

// ---------------- k2: LN + AE diag + dots, 4-row tiles --------------------
// grid 128, block 384
__global__ __launch_bounds__(384, 1)
void k2_ae(const float* __restrict__ enc_w,
           const float* __restrict__ enc_b,
           const float* __restrict__ dec_w,
           const float* __restrict__ dec_b,
           const float* __restrict__ ln_w,
           const float* __restrict__ ln_b) {
    const int r0 = blockIdx.x * 4;
    const int t  = threadIdx.x;           // 0..383
    __shared__ float zs[4 * XLD];         // 6.2 KB (LN'd in place)
    __shared__ float par[6144];           // 24.6 KB, reused enc->dec
    __shared__ float hs[4][HID];          // 3 KB
    __shared__ float rs1[4][12], rs2[4][12], mu_s[4], rsd_s[4];
    __shared__ float redd[4][12], redo[4][12];

    // stage raw z (1 float4/thread)
    {
        int r = t / 96, kk = (t % 96) * 4;
        *(float4*)&zs[r * XLD + kk] = *(const float4*)(g_z + (size_t)(r0 + r) * ZD + kk);
    }
    __syncthreads();

    // ---- LayerNorm the 4 rows in place ----
    const int wI = t >> 5, l = t & 31;
    float v[4];
#pragma unroll
    for (int r = 0; r < 4; r++) {
        v[r] = zs[r * XLD + t];
        float s = v[r], q = v[r] * v[r];
#pragma unroll
        for (int o = 16; o > 0; o >>= 1) {
            s += __shfl_down_sync(0xffffffffu, s, o);
            q += __shfl_down_sync(0xffffffffu, q, o);
        }
        if (l == 0) { rs1[r][wI] = s; rs2[r][wI] = q; }
    }
    __syncthreads();
    if (t < 4) {
        float s = 0.f, q = 0.f;
#pragma unroll
        for (int i = 0; i < 12; i++) { s += rs1[t][i]; q += rs2[t][i]; }
        float mu  = s * (1.0f / ZD);
        float var = q * (1.0f / ZD) - mu * mu;
        mu_s[t]  = mu;
        rsd_s[t] = rsqrtf(var + LN_EPS);
    }
    __syncthreads();
    {
        const float lw = ln_w[t], lb = ln_b[t];
#pragma unroll
        for (int r = 0; r < 4; r++)
            zs[r * XLD + t] = (v[r] - mu_s[r]) * rsd_s[r] * lw + lb;
    }
    __syncthreads();

    // ---- encoder GEMM: cg=t%48 (4 cols), kq=t/48 (8 slices of 48 k), 4 rows/thread
    {
        const int cg = t % 48, kq = t / 48, cc = cg * 4;
        float a[4][4];
#pragma unroll
        for (int r = 0; r < 4; r++)
#pragma unroll
            for (int c = 0; c < 4; c++) a[r][c] = 0.f;
        const float* wb = enc_w + (size_t)(kq * 48) * HID + cc;
        for (int kb = 0; kb < 48; kb += 8) {
            float4 w[8];
#pragma unroll
            for (int i = 0; i < 8; i++)
                w[i] = *(const float4*)(wb + (size_t)(kb + i) * HID);
#pragma unroll
            for (int i = 0; i < 8; i++) {
                const int k = kq * 48 + kb + i;
#pragma unroll
                for (int r = 0; r < 4; r++) {
                    float zv = zs[r * XLD + k];
                    a[r][0] += zv * w[i].x; a[r][1] += zv * w[i].y;
                    a[r][2] += zv * w[i].z; a[r][3] += zv * w[i].w;
                }
            }
        }
#pragma unroll
        for (int r = 0; r < 4; r++)
            *(float4*)&par[kq * 768 + r * HID + cc] =
                make_float4(a[r][0], a[r][1], a[r][2], a[r][3]);
    }
    __syncthreads();
    // reduce 8 partials -> hs (768 entries, 2/thread)
#pragma unroll
    for (int i = 0; i < 2; i++) {
        int idx = t + i * 384;
        int r = idx / HID, c = idx % HID;
        float h = enc_b[c];
#pragma unroll
        for (int q = 0; q < 8; q++) h += par[q * 768 + r * HID + c];
        hs[r][c] = gelu_exact(h);
    }
    __syncthreads();

    // ---- decoder GEMM: cg=t%96 (4 cols), kq=t/96 (4 slices of 48 u), 4 rows/thread
    {
        const int cg = t % 96, kq = t / 96, cc = cg * 4;
        float a[4][4];
#pragma unroll
        for (int r = 0; r < 4; r++)
#pragma unroll
            for (int c = 0; c < 4; c++) a[r][c] = 0.f;
        const float* wb = dec_w + (size_t)(kq * 48) * ZD + cc;
        for (int ub = 0; ub < 48; ub += 8) {
            float4 w[8];
#pragma unroll
            for (int i = 0; i < 8; i++)
                w[i] = *(const float4*)(wb + (size_t)(ub + i) * ZD);
#pragma unroll
            for (int i = 0; i < 8; i++) {
                const int u = kq * 48 + ub + i;
#pragma unroll
                for (int r = 0; r < 4; r++) {
                    float hv = hs[r][u];
                    a[r][0] += hv * w[i].x; a[r][1] += hv * w[i].y;
                    a[r][2] += hv * w[i].z; a[r][3] += hv * w[i].w;
                }
            }
        }
#pragma unroll
        for (int r = 0; r < 4; r++)
            *(float4*)&par[kq * 1536 + r * ZD + cc] =
                make_float4(a[r][0], a[r][1], a[r][2], a[r][3]);
    }
    __syncthreads();

    // ---- reduce + dots: thread t = col t, 4 rows ----
    const float db = dec_b[t];
    const float c0f = g_c0[t];
    float d[4], o[4];
#pragma unroll
    for (int r = 0; r < 4; r++) {
        float p = par[r * ZD + t] + par[1536 + r * ZD + t]
                + par[3072 + r * ZD + t] + par[4608 + r * ZD + t] + db;
        float zv = zs[r * XLD + t];
        d[r] = p * zv;
        o[r] = c0f * zv;
    }
#pragma unroll
    for (int r = 0; r < 4; r++) {
        float dd = d[r], oo = o[r];
#pragma unroll
        for (int s = 16; s > 0; s >>= 1) {
            dd += __shfl_down_sync(0xffffffffu, dd, s);
            oo += __shfl_down_sync(0xffffffffu, oo, s);
        }
        if (l == 0) { redd[r][wI] = dd; redo[r][wI] = oo; }
    }
    __syncthreads();
    if (t < 4) {
        float dd = 0.f, oo = 0.f;
#pragma unroll
        for (int i = 0; i < 12; i++) { dd += redd[t][i]; oo += redo[t][i]; }
        g_diag[r0 + t] = dd;
        g_off[r0 + t]  = oo;
    }
}

// ---------------- k3: softmax stats only (4 blocks x 128 threads) ---------
__global__ void k3_stats() {
    const int b = blockIdx.x;
    const int t = threadIdx.x;            // 0..127
    __shared__ float red[5];
    float off = g_off[b * NN + t];
    float dg  = g_diag[b * NN + t];
    float m = fmaxf(off, dg);
#pragma unroll
    for (int o = 16; o > 0; o >>= 1) m = fmaxf(m, __shfl_down_sync(0xffffffffu, m, o));
    const int w = t >> 5, l = t & 31;
    if (l == 0) red[w] = m;
    __syncthreads();
    if (t == 0) red[4] = fmaxf(fmaxf(red[0], red[1]), fmaxf(red[2], red[3]));
    __syncthreads();
    m = red[4];
    float a = expf(off - m), c = expf(dg - m);
    float e1 = a;
#pragma unroll
    for (int o = 16; o > 0; o >>= 1) e1 += __shfl_down_sync(0xffffffffu, e1, o);
    if (l == 0) red[w] = e1;
    __syncthreads();
    if (t == 0) red[4] = red[0] + red[1] + red[2] + red[3];
    __syncthreads();
    const float S = red[4];
    g_eo[b * NN + t] = a;
    g_wd[b * NN + t] = c - a;
    g_rD[b * NN + t] = 1.0f / (S - a + c);
}

// ---------------- k4: T + combine + final GEMM, tiled 16x96 ---------------
// grid 128: ct=bid&3 (96-col tile of 384), rt=bid>>2 (16-row tile)
__global__ __launch_bounds__(384, 1)
void k4_out(const float* __restrict__ V_w,
            const float* __restrict__ V_b,
            float* __restrict__ out) {
    const int ct = blockIdx.x & 3;
    const int rt = blockIdx.x >> 2;
    const int r0 = rt * 16;
    const int c0 = ct * 96;
    const int t  = threadIdx.x;
    const int b  = r0 / NN;               // 16 rows never straddle a batch

    __shared__ float sbuf[16 * XLD];      // us, then partials
    __shared__ float eo[NN], wd[16], rd[16];
    if (t < NN) eo[t] = g_eo[b * NN + t];
    if (t < 16) { wd[t] = g_wd[r0 + t]; rd[t] = g_rD[r0 + t]; }
    __syncthreads();

    // phase 1: T[t] and us rows (thread = col t)
    float T = 0.f;
    const float* xh = g_xh + (size_t)b * NN * ZD + t;
    for (int jb = 0; jb < NN; jb += 16) {
        float xv[16];
#pragma unroll
        for (int i = 0; i < 16; i++) xv[i] = xh[(size_t)(jb + i) * ZD];
#pragma unroll
        for (int i = 0; i < 16; i++) T += eo[jb + i] * xv[i];
    }
    {
        float xr[16];
#pragma unroll
        for (int r = 0; r < 16; r++) xr[r] = g_xh[(size_t)(r0 + r) * ZD + t];
#pragma unroll
        for (int r = 0; r < 16; r++)
            sbuf[r * XLD + t] = (T + wd[r] * xr[r]) * rd[r];
    }
    __syncthreads();

    // phase 2 GEMM: cg=t%24 (4 cols), rgrp=(t/24)&3 (4 rows), kq=t/96 (96 f)
    const int cg   = t % 24;
    const int rgrp = (t / 24) & 3;
    const int kq   = t / 96;
    const int cc   = cg * 4;
    float acc[4][4];
#pragma unroll
    for (int r = 0; r < 4; r++)
#pragma unroll
        for (int c = 0; c < 4; c++) acc[r][c] = 0.f;
    const float* wb = V_w + (size_t)(kq * 96) * FEAT + c0 + cc;
    const float* ub = &sbuf[(rgrp * 4) * XLD + kq * 96];
    for (int fb = 0; fb < 96; fb += 8) {
        float4 w[8];
#pragma unroll
        for (int i = 0; i < 8; i++)
            w[i] = *(const float4*)(wb + (size_t)(fb + i) * FEAT);
#pragma unroll
        for (int i = 0; i < 8; i++) {
#pragma unroll
            for (int r = 0; r < 4; r++) {
                float uv = ub[r * XLD + fb + i];
                acc[r][0] += uv * w[i].x; acc[r][1] += uv * w[i].y;
                acc[r][2] += uv * w[i].z; acc[r][3] += uv * w[i].w;
            }
        }
    }
    __syncthreads();   // us reads complete; reuse sbuf
#pragma unroll
    for (int r = 0; r < 4; r++)
        *(float4*)&sbuf[kq * 1536 + (rgrp * 4 + r) * 96 + cc] =
            make_float4(acc[r][0], acc[r][1], acc[r][2], acc[r][3]);
    __syncthreads();

#pragma unroll
    for (int i = 0; i < 4; i++) {
        int idx = t + i * 384;
        int r = idx / 96, c = idx % 96;
        out[(size_t)(r0 + r) * FEAT + c0 + c] =
            sbuf[r * 96 + c] + sbuf[1536 + r * 96 + c]
          + sbuf[3072 + r * 96 + c] + sbuf[4608 + r * 96 + c] + V_b[c0 + c];
    }
}

// ---------------- launch ---------------------------------------------------
extern "C" void kernel_launch(void* const* d_in, const int* in_sizes, int n_in,
                              void* d_out, int out_size) {
    const float* x     = (const float*)d_in[0];
    const float* U_w   = (const float*)d_in[1];
    const float* U_b   = (const float*)d_in[2];
    const float* ln_w  = (const float*)d_in[3];
    const float* ln_b  = (const float*)d_in[4];
    const float* enc_w = (const float*)d_in[5];
    const float* enc_b = (const float*)d_in[6];
    const float* dec_w = (const float*)d_in[7];
    const float* dec_b = (const float*)d_in[8];
    const float* V_w   = (const float*)d_in[9];
    const float* V_b   = (const float*)d_in[10];
    float* out = (float*)d_out;

    k1_gemmU<<<257, 384>>>(x, U_w, U_b, enc_b, dec_w, dec_b);
    k2_ae<<<128, 384>>>(enc_w, enc_b, dec_w, dec_b, ln_w, ln_b);
    k3_stats<<<NB, NN>>>();
    k4_out<<<128, 384>>>(V_w, V_b, out);
}